// round 17
// baseline (speedup 1.0000x reference)
#include <cuda_runtime.h>
#include <cstdint>
#include <math.h>

// ---------------- problem constants ----------------
#define NS    5
#define NG    70
#define NBC   40
#define HP    150          // padded grid (70 + 2*40)
#define NT    1000
#define ISZ   41           // source row (padded coords)
#define IGZ   41           // receiver row
#define SW    160          // smem row stride (floats); interior col j at x=j+4
#define CW    152          // coeff row stride
#define GPR   38           // 4-wide groups per row
#define CLUSTER 8
#define TPB   896          // 28 warps: bands 3 + 7*3 + 4
#define MAXNR 19
#define ROWS_S (MAXNR + 4)     // 23 smem rows per CTA (2 halo each side)

#define FIELD_FLOATS (ROWS_S * SW)                           // 3680
#define MBAR_OFF (2 * FIELD_FLOATS + 3 * MAXNR * CW + NT)    // float idx of mbars
#define SMEM_FLOATS (MBAR_OFF + 8)                           // 4 x u64 mbarriers
#define SMEM_BYTES  (SMEM_FLOATS * 4)

typedef unsigned long long u64;

__device__ float g_temp1[2 * HP * CW];
__device__ float g_temp2[2 * HP * CW];
__device__ float g_alpha[2 * HP * CW];
__device__ float g_src[NT];
__device__ float g_bsrc[2 * NS];

__constant__ int c_isx[NS]        = {40, 57, 74, 92, 109};
__constant__ int c_start[CLUSTER] = {0, 19, 38, 57, 76, 95, 114, 132};
__constant__ int c_nr[CLUSTER]    = {19, 19, 19, 19, 19, 19, 18, 18};

// ---------------- ptx helpers ----------------
__device__ __forceinline__ unsigned int smem_u32(const void* p) {
    return (unsigned int)__cvta_generic_to_shared(p);
}
__device__ __forceinline__ unsigned int mapa_u32(unsigned int a, unsigned int r) {
    unsigned int d;
    asm("mapa.shared::cluster.u32 %0, %1, %2;" : "=r"(d) : "r"(a), "r"(r));
    return d;
}
__device__ __forceinline__ unsigned int my_ctarank() {
    unsigned int r;
    asm("mov.u32 %0, %%cluster_ctarank;" : "=r"(r));
    return r;
}
__device__ __forceinline__ void stc_b64(unsigned int a, u64 v) {
    asm volatile("st.shared::cluster.b64 [%0], %1;" :: "r"(a), "l"(v) : "memory");
}
__device__ __forceinline__ void named_bar(int id, int cnt) {
    asm volatile("bar.sync %0, %1;" :: "r"(id), "r"(cnt) : "memory");
}
__device__ __forceinline__ void mbar_init(unsigned int a, unsigned int count) {
    asm volatile("mbarrier.init.shared.b64 [%0], %1;" :: "r"(a), "r"(count) : "memory");
}
__device__ __forceinline__ void mbar_arrive_remote(unsigned int a) {
    asm volatile("mbarrier.arrive.release.cluster.shared::cluster.b64 _, [%0];"
                 :: "r"(a) : "memory");
}
__device__ __forceinline__ void mbar_wait_parity(unsigned int a, int parity) {
    unsigned int done;
    asm volatile(
        "{\n\t.reg .pred p;\n\t"
        "mbarrier.try_wait.parity.acquire.cluster.shared::cta.b64 p, [%1], %2;\n\t"
        "selp.b32 %0, 1, 0, p;\n\t}"
        : "=r"(done) : "r"(a), "r"((unsigned int)parity) : "memory");
    while (!done) {
        asm volatile(
            "{\n\t.reg .pred p;\n\t"
            "mbarrier.try_wait.parity.acquire.cluster.shared::cta.b64 p, [%1], %2, 0x989680;\n\t"
            "selp.b32 %0, 1, 0, p;\n\t}"
            : "=r"(done) : "r"(a), "r"((unsigned int)parity) : "memory");
    }
}

// ---- packed f32x2 helpers ----
__device__ __forceinline__ u64 pk2(float lo, float hi) {
    u64 r; asm("mov.b64 %0, {%1, %2};" : "=l"(r) : "f"(lo), "f"(hi)); return r;
}
__device__ __forceinline__ void upk2(u64 v, float& lo, float& hi) {
    asm("mov.b64 {%0, %1}, %2;" : "=f"(lo), "=f"(hi) : "l"(v));
}
__device__ __forceinline__ u64 add2(u64 a, u64 b) {
    u64 r; asm("add.rn.f32x2 %0, %1, %2;" : "=l"(r) : "l"(a), "l"(b)); return r;
}
__device__ __forceinline__ u64 mul2(u64 a, u64 b) {
    u64 r; asm("mul.rn.f32x2 %0, %1, %2;" : "=l"(r) : "l"(a), "l"(b)); return r;
}
__device__ __forceinline__ u64 fma2(u64 a, u64 b, u64 c) {
    u64 r; asm("fma.rn.f32x2 %0, %1, %2, %3;" : "=l"(r) : "l"(a), "l"(b), "l"(c)); return r;
}

// ---------------- init: coefficients, source wavelet, bsrc ----------------
__global__ void fwi_init(const float* __restrict__ v) {
    const int b   = blockIdx.x;
    const int tid = threadIdx.x;
    __shared__ float red[256];

    const float* vb = v + b * 70 * 70;

    float m = 1e30f;
    for (int k = tid; k < 70 * 70; k += 256) m = fminf(m, vb[k]);
    red[tid] = m;
    __syncthreads();
    for (int s = 128; s > 0; s >>= 1) {
        if (tid < s) red[tid] = fminf(red[tid], red[tid + s]);
        __syncthreads();
    }
    const float vmin  = red[0];
    const float kappa = ((3.0f * vmin) * 16.118095650958319f) / 780.0f;

    for (int k = tid; k < HP * CW; k += 256) {
        const int i = k / CW;
        const int j = k - i * CW;
        float t1 = 0.f, t2 = 0.f, al = 0.f;
        if (j < HP) {
            const int vi = min(max(i - NBC, 0), 69);
            const int vj = min(max(j - NBC, 0), 69);
            const float vp = vb[vi * 70 + vj];
            const float a  = vp * 0.001f / 10.0f;
            al = a * a;
            float r2 = 0.f;
            int rk = -1;
            if      (j < NBC)        rk = (NBC - 1) - j;
            else if (j >= HP - NBC)  rk = j - (HP - NBC);
            else if (i < NBC)        rk = (NBC - 1) - i;
            else if (i >= HP - NBC)  rk = i - (HP - NBC);
            if (rk >= 0) {
                const float t = ((float)rk * 10.0f) / 390.0f;
                r2 = t * t;
            }
            const float kdt = (kappa * r2) * 0.001f;
            t1 = 2.0f - 5.0f * al - kdt;
            t2 = 1.0f - kdt;
        }
        const int off = b * HP * CW + k;
        g_temp1[off] = t1;
        g_temp2[off] = t2;
        g_alpha[off] = al;
    }

    if (tid < NS) {
        const int isxs = c_isx[tid];
        const int vi = min(max(ISZ  - NBC, 0), 69);
        const int vj = min(max(isxs - NBC, 0), 69);
        const float bv = vb[vi * 70 + vj] * 0.001f;
        g_bsrc[b * NS + tid] = bv * bv;
    }

    if (b == 0) {
        for (int t = tid; t < NT; t += 256) {
            float w = 0.f;
            if (t < 147) {
                const double a  = (73.0 - (double)t) * 15.0 * 0.001 * 3.141592653589793;
                const double be = a * a;
                w = (float)((1.0 - 2.0 * be) * exp(-be));
            }
            g_src[t] = w;
        }
    }
}

// ---------------- main: 8-CTA cluster, wavefront row-bands, packed math ----------------
__global__ void __launch_bounds__(TPB, 1) __cluster_dims__(CLUSTER, 1, 1)
fwi_kernel(float* __restrict__ out) {
    extern __shared__ float sm[];
    float* buf0 = sm;
    float* buf1 = sm + FIELD_FLOATS;
    float* sT1  = sm + 2 * FIELD_FLOATS;
    float* sT2  = sT1 + MAXNR * CW;
    float* sAL  = sT2 + MAXNR * CW;
    float* srcs = sAL + MAXNR * CW;

    const int tid  = threadIdx.x;
    const int cid  = blockIdx.x / CLUSTER;
    const unsigned int rank = my_ctarank();
    const int b = cid / NS, s = cid - b * NS;

    const int start = c_start[rank];
    const int nr    = c_nr[rank];
    const unsigned int rp = (rank + CLUSTER - 1) & (CLUSTER - 1);
    const unsigned int rn = (rank + 1) & (CLUSTER - 1);
    const int nr_p = c_nr[rp];

    const unsigned int mb_u = smem_u32(sm + MBAR_OFF);
    const unsigned int b0_u = smem_u32(buf0);
    const unsigned int b1_u = smem_u32(buf1);

    // ---- init smem ----
    for (int k = tid; k < 2 * FIELD_FLOATS; k += TPB) sm[k] = 0.f;
    {
        const float* GT1 = g_temp1 + (b * HP + start) * CW;
        const float* GT2 = g_temp2 + (b * HP + start) * CW;
        const float* GAL = g_alpha + (b * HP + start) * CW;
        const int n = nr * CW;
        for (int k = tid; k < n; k += TPB) {
            sT1[k] = GT1[k];
            sT2[k] = GT2[k];
            sAL[k] = GAL[k];
        }
        for (int k = tid; k < NT; k += TPB) srcs[k] = g_src[k];
    }
    if (tid == 0) {
        mbar_init(mb_u + 0,  4);   // M_top[0]: prev band8 (4 warps), buffer 0
        mbar_init(mb_u + 8,  4);   // M_top[1]
        mbar_init(mb_u + 16, 3);   // M_bot[0]: next band0 (3 warps), buffer 0
        mbar_init(mb_u + 24, 3);   // M_bot[1]
        asm volatile("fence.mbarrier_init.release.cluster;" ::: "memory");
    }
    __syncthreads();

    // ---- band geometry (warp-aligned row bands) ----
    const int w    = tid >> 5;
    const int band = (w < 3) ? 0 : (w < 24) ? (1 + (w - 3) / 3) : 8;
    const int bfw  = (band == 0) ? 0 : (band < 8) ? 3 * band : 24;
    const int lg   = tid - bfw * 32;
    const int nrowsB = (band == 8) ? 3 : 2;
    const int row  = ((band == 8) ? 16 : 2 * band) + lg / GPR;
    const int g    = lg - (lg / GPR) * GPR;
    const int j0   = g * 4;
    const bool active = (lg < nrowsB * GPR) && (row < nr);

    const int boff = (row + 2) * SW + j0;
    const int cb   = row * CW + j0;

    const bool pushP = active && (row < 2);           // band0 -> prev bottom halo
    const bool pushN = active && (row >= nr - 2);     // band8 -> next top halo
    const bool lastg = (g == GPR - 1);
    const unsigned int ppo = (unsigned int)(((nr_p + 2 + row) * SW + j0 + 4) * 4);
    const unsigned int pno = (unsigned int)(((row - (nr - 2)) * SW + j0 + 4) * 4);

    // hoisted packed coefficients
    u64 t101 = 0, t123 = 0, nt201 = 0, nt223 = 0, al01 = 0, al23 = 0;
    if (active) {
        const float4 t1v = *(const float4*)(sT1 + cb);
        const float4 t2v = *(const float4*)(sT2 + cb);
        const float4 alv = *(const float4*)(sAL + cb);
        t101  = pk2(t1v.x, t1v.y);   t123  = pk2(t1v.z, t1v.w);
        nt201 = pk2(-t2v.x, -t2v.y); nt223 = pk2(-t2v.z, -t2v.w);
        al01  = pk2(alv.x, alv.y);   al23  = pk2(alv.z, alv.w);
    }
    const float C2v = (float)( 4.0 / 3.0);
    const float C3v = (float)(-1.0 / 12.0);
    const u64 C2p = pk2(C2v, C2v);
    const u64 C3p = pk2(C3v, C3v);

    asm volatile("barrier.cluster.arrive.aligned;" ::: "memory");
    asm volatile("barrier.cluster.wait.aligned;"   ::: "memory");

    // remote addresses (per target buffer)
    const unsigned int prevB0 = mapa_u32(b0_u, rp), prevB1 = mapa_u32(b1_u, rp);
    const unsigned int nextB0 = mapa_u32(b0_u, rn), nextB1 = mapa_u32(b1_u, rn);
    const unsigned int aBotPrev0 = mapa_u32(mb_u + 16, rp);
    const unsigned int aBotPrev1 = mapa_u32(mb_u + 24, rp);
    const unsigned int aTopNext0 = mapa_u32(mb_u + 0,  rn);
    const unsigned int aTopNext1 = mapa_u32(mb_u + 8,  rn);

    const int  isxs    = c_isx[s];
    const int  dsel    = isxs - j0;
    const bool srcflag = active && (start + row == ISZ) && (dsel >= 0) && (dsel < 4);

    // receivers: written from registers by the owning row's threads
    const bool recband = active && (start + row == IGZ);
    const bool r0ok = recband && (j0 + 0 >= 40) && (j0 + 0 <= 109);
    const bool r1ok = recband && (j0 + 1 >= 40) && (j0 + 1 <= 109);
    const bool r2ok = recband && (j0 + 2 >= 40) && (j0 + 2 <= 109);
    const bool r3ok = recband && (j0 + 3 >= 40) && (j0 + 3 <= 109);
    const float bsrcv = g_bsrc[b * NS + s];
    float* __restrict__ orow = out + (size_t)(b * NS + s) * NT * NG + (j0 - 40);

    const float* pcur = buf1;   // p(t)
    float*       pnew = buf0;   // p(t+1) target; buffer W=t&1

    // packed register time-cache: cur = p(t), old = p(t-1)
    u64 cur01 = 0, cur23 = 0, old01 = 0, old23 = 0;

    const int cntLo = (band == 8) ? 224 : 192;    // pair (band-1, band)
    const int cntHi = (band == 7) ? 224 : 192;    // pair (band, band+1)

    for (int t = 0; t < NT; ++t) {
        const int W = t & 1;
        const float srcval = bsrcv * srcs[t];

        // ---- local wavefront sync: only adjacent bands rendezvous ----
        if (band > 0) named_bar(band, cntLo);
        if (band < 8) named_bar(band + 1, cntHi);

        // ---- edge bands: wait for neighbor CTA's step t-1 pushes ----
        if (t > 0) {
            const int Wp = (t - 1) & 1;
            const int par = ((t - 1) >> 1) & 1;
            if (band == 0)      mbar_wait_parity(mb_u + 8 * Wp, par);
            else if (band == 8) mbar_wait_parity(mb_u + 16 + 8 * Wp, par);
        }

        if (active) {
            // packed loads: eL=(cc2,cc3), eR=(cc8,cc9), z-rows as b64 lane pairs
            const u64 eL = *(const u64*)(pcur + boff + 2);
            const u64 eR = *(const u64*)(pcur + boff + 8);
            const ulonglong2 zm2v = *(const ulonglong2*)(pcur + boff - 2 * SW + 4);
            const ulonglong2 zm1v = *(const ulonglong2*)(pcur + boff -     SW + 4);
            const ulonglong2 zp1v = *(const ulonglong2*)(pcur + boff +     SW + 4);
            const ulonglong2 zp2v = *(const ulonglong2*)(pcur + boff + 2 * SW + 4);

            u64 c23 = cur23;
            if (lastg) c23 = *(const u64*)(pcur + boff + 6);

            float cc2, cc3, cc4, cc5, cc6, cc7, cc8, cc9;
            upk2(eL, cc2, cc3);
            upk2(cur01, cc4, cc5);
            upk2(c23, cc6, cc7);
            upk2(eR, cc8, cc9);
            const u64 Pa = pk2(cc3, cc4);
            const u64 Pb = pk2(cc5, cc6);
            const u64 Rb = pk2(cc7, cc8);

            // l01 / l23 (pairwise sums, then C2*s + C3*s via mul+fma)
            const u64 s12a = add2(add2(Pa, Pb),     add2(zm1v.x, zp1v.x));
            const u64 s34a = add2(add2(eL, c23),    add2(zm2v.x, zp2v.x));
            const u64 l01  = fma2(C3p, s34a, mul2(C2p, s12a));
            const u64 s12b = add2(add2(Pb, Rb),     add2(zm1v.y, zp1v.y));
            const u64 s34b = add2(add2(cur01, eR),  add2(zm2v.y, zp2v.y));
            const u64 l23  = fma2(C3p, s34b, mul2(C2p, s12b));

            // n = t1*cur - t2*old + alpha*l  (packed FFMA chain)
            u64 n01 = fma2(al01, l01, fma2(nt201, old01, mul2(t101, cur01)));
            u64 n23 = fma2(al23, l23, fma2(nt223, old23, mul2(t123, c23)));

            if (srcflag) {
                float a, q;
                if (dsel < 2) {
                    upk2(n01, a, q);
                    if (dsel == 0) a += srcval; else q += srcval;
                    n01 = pk2(a, q);
                } else {
                    upk2(n23, a, q);
                    if (dsel == 2) a += srcval; else q += srcval;
                    n23 = pk2(a, q);
                }
            }

            if (lastg) {
                *(u64*)(pnew + boff + 4)      = n01;
                *(u64*)(pnew + boff - j0 + 2) = n01;
            } else {
                *(u64*)(pnew + boff + 4) = n01;
                *(u64*)(pnew + boff + 6) = n23;
                if (g == 0)
                    *(u64*)(pnew + boff + 154) = n01;
            }

            if (pushP) {
                const unsigned int a = (W ? prevB1 : prevB0) + ppo;
                stc_b64(a,     n01);
                stc_b64(a + 8, n23);
            } else if (pushN) {
                const unsigned int a = (W ? nextB1 : nextB0) + pno;
                stc_b64(a,     n01);
                stc_b64(a + 8, n23);
            }

            if (recband) {
                float a, q, c, d;
                upk2(n01, a, q);
                upk2(n23, c, d);
                float* o = orow + t * NG;
                if (r0ok) o[0] = a;
                if (r1ok) o[1] = q;
                if (r2ok) o[2] = c;
                if (r3ok) o[3] = d;
            }

            old01 = cur01; old23 = cur23;
            cur01 = n01;   cur23 = n23;
        }

        // ---- edge bands: per-warp arrive on the buffer-W mbar ----
        if (band == 0) {
            __syncwarp();
            if ((tid & 31) == 0) mbar_arrive_remote(W ? aBotPrev1 : aBotPrev0);
        } else if (band == 8) {
            __syncwarp();
            if ((tid & 31) == 0) mbar_arrive_remote(W ? aTopNext1 : aTopNext0);
        }

        float* tmp = pnew; pnew = (float*)pcur; pcur = tmp;
    }

    asm volatile("barrier.cluster.arrive.aligned;" ::: "memory");
    asm volatile("barrier.cluster.wait.aligned;"   ::: "memory");
}

// ---------------- launch ----------------
extern "C" void kernel_launch(void* const* d_in, const int* in_sizes, int n_in,
                              void* d_out, int out_size) {
    const float* v = (const float*)d_in[0];
    float* out = (float*)d_out;

    cudaFuncSetAttribute(fwi_kernel, cudaFuncAttributeMaxDynamicSharedMemorySize,
                         SMEM_BYTES);

    fwi_init<<<2, 256>>>(v);
    fwi_kernel<<<2 * NS * CLUSTER, TPB, SMEM_BYTES>>>(out);
}